// round 7
// baseline (speedup 1.0000x reference)
#include <cuda_runtime.h>
#include <cstdint>

#define B_      8
#define V_      50000
#define C_      256
#define PC_     64
#define K_      9
#define KIN1_   (K_ * PC_)          // 576
#define M_TOTAL (B_ * V_)           // 400000
#define TILE_M  64

// ---- SMEM layout (32-bit words), TILE_M = 64 ----
// Phase 1:  offs[576] | As1[64*68] | Bs1[64*68]   -> [0, 9280)
// Phase 2 overlays [0, 9280): Bs2[256*36] = 9216 words
// Af[64*260] at 9280 (disjoint). Total 25920 words = 103680 B -> 2 CTAs/SM.
#define OFFS_OFF   0
#define AS1_OFF    576
#define BS1_OFF    (576 + 64*68)        // 4928
#define BS2_OFF    0
#define AF_OFF     9280
#define AS1_ST     68                   // 68 % 32 == 4 -> conflict-free frags
#define BS1_ST     68
#define BS2_ST     36                   // 36 % 32 == 4
#define AF_ST      260                  // 260 % 32 == 4
#define SMEM_WORDS (AF_OFF + TILE_M*AF_ST)   // 25920 words

// Round-to-nearest fp32 -> tf32 bit pattern (pure bit math).
__device__ __forceinline__ unsigned f2tf(float f) {
    unsigned u = __float_as_uint(f);
    return (u + 0xFFFu + ((u >> 13) & 1u)) & 0xFFFFE000u;
}

__device__ __forceinline__ void mma8(float* c, const unsigned* a, unsigned u0, unsigned u1) {
    asm volatile(
        "mma.sync.aligned.m16n8k8.row.col.f32.tf32.tf32.f32 "
        "{%0,%1,%2,%3}, {%4,%5,%6,%7}, {%8,%9}, {%0,%1,%2,%3};"
        : "+f"(c[0]), "+f"(c[1]), "+f"(c[2]), "+f"(c[3])
        : "r"(a[0]), "r"(a[1]), "r"(a[2]), "r"(a[3]), "r"(u0), "r"(u1));
}

__global__ void __launch_bounds__(256, 2)
fused_spiral(const float* x,
             const int* idx,            // int32 (JAX x64 disabled)
             const float* W1,
             const float* b1,
             const float* W2,
             const float* b2,
             float* out)
{
    extern __shared__ unsigned sm[];
    int*      offs = (int*)(sm + OFFS_OFF);
    unsigned* As1  = sm + AS1_OFF;
    unsigned* Bs1  = sm + BS1_OFF;
    unsigned* Bs2  = sm + BS2_OFF;
    unsigned* Af   = sm + AF_OFF;

    const int tid = threadIdx.x;
    const int m0  = blockIdx.x * TILE_M;
    const int warp = tid >> 5, lane = tid & 31;
    const int lg = lane >> 2, lq = lane & 3;

    // ---- Gather row offsets (elements into x); defensive clamp ----
    for (int i = tid; i < TILE_M * K_; i += 256) {
        int r = i / K_;
        int k = i - r * K_;
        int m = m0 + r;
        int b = m / V_;
        int v = m - b * V_;
        int id = idx[v * K_ + k];
        id = id < 0 ? 0 : (id >= V_ ? V_ - 1 : id);
        offs[i] = (b * V_ + id) * C_;
    }

    // ---- Preload x untouched cols [64,256) into Af (tf32) ----
    // row = tid & 63, part = tid >> 6 (0..3): 12 float4 each. Conflict-free STS.
    {
        const int row = tid & 63, part = tid >> 6;
        const float* src = x + (size_t)(m0 + row) * C_ + PC_ + part * 48;
        unsigned* dst = Af + row * AF_ST + PC_ + part * 48;
        #pragma unroll
        for (int j = 0; j < 12; j++) {
            float4 v4 = *(const float4*)(src + j * 4);
            *(uint4*)(dst + j * 4) =
                make_uint4(f2tf(v4.x), f2tf(v4.y), f2tf(v4.z), f2tf(v4.w));
        }
    }
    __syncthreads();

    // ================= Phase 1: gather + GEMM1 (64x64, K=576) =================
    // 8 warps: wm1 = warp&1 -> rows wm1*32; wn1 = warp>>1 -> cols wn1*16.
    const int wm1 = warp & 1;
    const int wn1 = warp >> 1;
    float acc1[2][2][4];
    #pragma unroll
    for (int i = 0; i < 2; i++)
        #pragma unroll
        for (int j = 0; j < 2; j++)
            #pragma unroll
            for (int l = 0; l < 4; l++) acc1[i][j][l] = 0.f;

    const int lrow = tid & 63, lqc = tid >> 6;   // loader: row, 16-float chunk

    for (int kc = 0; kc < K_; kc++) {
        {   // A slab: 64 gathered rows x 64 floats, tf32
            const float* src = x + offs[lrow * K_ + kc] + lqc * 16;
            unsigned* dA = As1 + lrow * AS1_ST + lqc * 16;
            #pragma unroll
            for (int j = 0; j < 4; j++) {
                float4 v4 = *(const float4*)(src + j * 4);
                *(uint4*)(dA + j * 4) =
                    make_uint4(f2tf(v4.x), f2tf(v4.y), f2tf(v4.z), f2tf(v4.w));
            }
        }
        {   // B slab: W1[out=lrow][kc*64 ..]
            const float* src = W1 + lrow * KIN1_ + kc * PC_ + lqc * 16;
            unsigned* dB = Bs1 + lrow * BS1_ST + lqc * 16;
            #pragma unroll
            for (int j = 0; j < 4; j++) {
                float4 v4 = *(const float4*)(src + j * 4);
                *(uint4*)(dB + j * 4) =
                    make_uint4(f2tf(v4.x), f2tf(v4.y), f2tf(v4.z), f2tf(v4.w));
            }
        }
        __syncthreads();

        #pragma unroll
        for (int kk = 0; kk < PC_; kk += 8) {
            unsigned a[2][4];
            #pragma unroll
            for (int ms = 0; ms < 2; ms++) {
                const unsigned* p = As1 + (wm1 * 32 + ms * 16 + lg) * AS1_ST + kk + lq;
                a[ms][0] = p[0];
                a[ms][1] = p[8 * AS1_ST];
                a[ms][2] = p[4];
                a[ms][3] = p[8 * AS1_ST + 4];
            }
            #pragma unroll
            for (int ns = 0; ns < 2; ns++) {
                const unsigned* p = Bs1 + (wn1 * 16 + ns * 8 + lg) * BS1_ST + kk + lq;
                unsigned u0 = p[0], u1 = p[4];
                mma8(acc1[0][ns], a[0], u0, u1);
                mma8(acc1[1][ns], a[1], u0, u1);
            }
        }
        __syncthreads();
    }

    // ---- P epilogue: + b1, tf32, into Af cols [0,64) ----
    #pragma unroll
    for (int ms = 0; ms < 2; ms++) {
        #pragma unroll
        for (int ns = 0; ns < 2; ns++) {
            int row = wm1 * 32 + ms * 16 + lg;
            int col = wn1 * 16 + ns * 8 + lq * 2;
            float bv0 = b1[col], bv1 = b1[col + 1];
            *(uint2*)(Af + row * AF_ST + col) =
                make_uint2(f2tf(acc1[ms][ns][0] + bv0), f2tf(acc1[ms][ns][1] + bv1));
            *(uint2*)(Af + (row + 8) * AF_ST + col) =
                make_uint2(f2tf(acc1[ms][ns][2] + bv0), f2tf(acc1[ms][ns][3] + bv1));
        }
    }

    // ================= Phase 2: out = Af(64x256) @ W2^T + b2 =================
    // 8 warps: wm2 = warp&1 -> rows wm2*32; wn2 = warp>>1 -> cols wn2*64.
    const int wm2 = warp & 1;
    const int wn2 = warp >> 1;
    float acc2[2][8][4];
    #pragma unroll
    for (int i = 0; i < 2; i++)
        #pragma unroll
        for (int j = 0; j < 8; j++)
            #pragma unroll
            for (int l = 0; l < 4; l++) acc2[i][j][l] = 0.f;

    for (int kc = 0; kc < 8; kc++) {
        __syncthreads();   // phase-1 epilogue done / prior Bs2 readers done
        {   // B slab: W2[out=tid][kc*32 ..+32): one full 128B sliver per thread
            const float* src = W2 + (size_t)tid * C_ + kc * 32;
            unsigned* dB = Bs2 + tid * BS2_ST;
            #pragma unroll
            for (int j = 0; j < 8; j++) {
                float4 v4 = *(const float4*)(src + j * 4);
                *(uint4*)(dB + j * 4) =
                    make_uint4(f2tf(v4.x), f2tf(v4.y), f2tf(v4.z), f2tf(v4.w));
            }
        }
        __syncthreads();

        #pragma unroll
        for (int kk = 0; kk < 32; kk += 8) {
            unsigned a[2][4];
            #pragma unroll
            for (int ms = 0; ms < 2; ms++) {
                const unsigned* p =
                    Af + (wm2 * 32 + ms * 16 + lg) * AF_ST + kc * 32 + kk + lq;
                a[ms][0] = p[0];
                a[ms][1] = p[8 * AF_ST];
                a[ms][2] = p[4];
                a[ms][3] = p[8 * AF_ST + 4];
            }
            #pragma unroll
            for (int ns = 0; ns < 8; ns++) {
                const unsigned* p = Bs2 + (wn2 * 64 + ns * 8 + lg) * BS2_ST + kk + lq;
                unsigned u0 = p[0], u1 = p[4];
                mma8(acc2[0][ns], a[0], u0, u1);
                mma8(acc2[1][ns], a[1], u0, u1);
            }
        }
    }

    // Epilogue: + b2 (global, L2-hot), store out
    #pragma unroll
    for (int ms = 0; ms < 2; ms++) {
        #pragma unroll
        for (int ns = 0; ns < 8; ns++) {
            int row = m0 + wm2 * 32 + ms * 16 + lg;
            int col = wn2 * 64 + ns * 8 + lq * 2;
            float bv0 = b2[col], bv1 = b2[col + 1];
            *(float2*)(out + (size_t)row * C_ + col) =
                make_float2(acc2[ms][ns][0] + bv0, acc2[ms][ns][1] + bv1);
            *(float2*)(out + (size_t)(row + 8) * C_ + col) =
                make_float2(acc2[ms][ns][2] + bv0, acc2[ms][ns][3] + bv1);
        }
    }
}

extern "C" void kernel_launch(void* const* d_in, const int* in_sizes, int n_in,
                              void* d_out, int out_size) {
    const float* x   = (const float*)d_in[0];
    const int*   idx = (const int*)d_in[1];
    const float* W1  = (const float*)d_in[2];
    const float* b1  = (const float*)d_in[3];
    const float* W2  = (const float*)d_in[4];
    const float* b2  = (const float*)d_in[5];
    float*       out = (float*)d_out;

    const int smem = SMEM_WORDS * 4;   // 103680 bytes
    cudaFuncSetAttribute(fused_spiral, cudaFuncAttributeMaxDynamicSharedMemorySize, smem);
    fused_spiral<<<M_TOTAL / TILE_M, 256, smem>>>(x, idx, W1, b1, W2, b2, out);
}

// round 9
// speedup vs baseline: 1.5071x; 1.5071x over previous
#include <cuda_runtime.h>
#include <cstdint>

#define B_      8
#define V_      50000
#define C_      256
#define PC_     64
#define K_      9
#define KIN1_   (K_ * PC_)          // 576
#define M_TOTAL (B_ * V_)           // 400000
#define TILE_M  128

// ---- SMEM layout (32-bit words) — identical to round 6 ----
#define OFFS_OFF   0
#define AS1_OFF    1152
#define BS1_OFF    (1152 + 128*68)      // 9856
#define BS2_OFF    0
#define BIAS2_OFF  4608
#define AF_OFF     14208
#define AS1_ST     68
#define BS1_ST     68
#define BS2_ST     36
#define AF_ST      260                  // 260 % 32 == 4 -> conflict-free frags
#define SMEM_WORDS (AF_OFF + 128*AF_ST) // 47488 words = 189952 bytes

// Round-to-nearest fp32 -> tf32 bit pattern (pure bit math).
__device__ __forceinline__ unsigned f2tf(float f) {
    unsigned u = __float_as_uint(f);
    return (u + 0xFFFu + ((u >> 13) & 1u)) & 0xFFFFE000u;
}
__device__ __forceinline__ uint4 f2tf4(float4 v) {
    return make_uint4(f2tf(v.x), f2tf(v.y), f2tf(v.z), f2tf(v.w));
}

__device__ __forceinline__ void mma8(float* c, const unsigned* a, unsigned u0, unsigned u1) {
    asm volatile(
        "mma.sync.aligned.m16n8k8.row.col.f32.tf32.tf32.f32 "
        "{%0,%1,%2,%3}, {%4,%5,%6,%7}, {%8,%9}, {%0,%1,%2,%3};"
        : "+f"(c[0]), "+f"(c[1]), "+f"(c[2]), "+f"(c[3])
        : "r"(a[0]), "r"(a[1]), "r"(a[2]), "r"(a[3]), "r"(u0), "r"(u1));
}

__global__ void __launch_bounds__(256, 1)
fused_spiral(const float* x,
             const int* idx,            // int32 (JAX x64 disabled)
             const float* W1,
             const float* b1,
             const float* W2,
             const float* b2,
             float* out)
{
    extern __shared__ unsigned sm[];
    int*      offs  = (int*)(sm + OFFS_OFF);
    unsigned* As1   = sm + AS1_OFF;
    unsigned* Bs1   = sm + BS1_OFF;
    unsigned* Bs2   = sm + BS2_OFF;
    float*    bias2 = (float*)(sm + BIAS2_OFF);
    unsigned* Af    = sm + AF_OFF;

    const int tid = threadIdx.x;
    const int m0  = blockIdx.x * TILE_M;
    const int warp = tid >> 5, lane = tid & 31;
    const int wm = warp & 3;                 // m group: wm*32
    const int wn = warp >> 2;                // n group (ph1: wn*32, ph2: wn*64)
    const int lg = lane >> 2, lq = lane & 3;

    // ---- Gather row offsets (elements into x); defensive clamp ----
    for (int i = tid; i < TILE_M * K_; i += 256) {
        int r = i / K_;
        int k = i - r * K_;
        int m = m0 + r;
        int b = m / V_;
        int v = m - b * V_;
        int id = idx[v * K_ + k];
        id = id < 0 ? 0 : (id >= V_ ? V_ - 1 : id);
        offs[i] = (b * V_ + id) * C_;
    }

    // ---- Preload x untouched cols [64,256) into Af (tf32) ----
    for (int q = tid; q < 128 * 48; q += 256) {
        int row = q / 48;
        int c4  = q - row * 48;
        float4 v4 = *(const float4*)(x + (size_t)(m0 + row) * C_ + PC_ + c4 * 4);
        *(uint4*)(Af + row * AF_ST + PC_ + c4 * 4) = f2tf4(v4);
    }
    __syncthreads();

    // ================= Phase 1: gather + GEMM1 (128x64, K=576) =================
    float acc1[2][4][4];
    #pragma unroll
    for (int i = 0; i < 2; i++)
        #pragma unroll
        for (int j = 0; j < 4; j++)
            #pragma unroll
            for (int l = 0; l < 4; l++) acc1[i][j][l] = 0.f;

    const int lr = tid >> 1, lh = tid & 1;   // A loader: row, half(32 floats)
    const int lo = tid >> 2, lq4 = tid & 3;  // B loader: out-row, quarter

    float4 pa[8], pb[4];                     // prefetch registers
    {   // prologue: prefetch chunk 0
        const float4* sA = (const float4*)(x + offs[lr * K_ + 0]) + lh * 8;
        #pragma unroll
        for (int j = 0; j < 8; j++) pa[j] = sA[j];
        const float4* sB = (const float4*)(W1 + lo * KIN1_);
        #pragma unroll
        for (int j = 0; j < 4; j++) pb[j] = sB[lq4 * 4 + j];
    }

    for (int kc = 0; kc < K_; kc++) {
        {   // STS prefetched A slab (tf32 convert at store)
            unsigned* dA = As1 + lr * AS1_ST + lh * 32;
            #pragma unroll
            for (int j = 0; j < 8; j++) *(uint4*)(dA + j * 4) = f2tf4(pa[j]);
            unsigned* dB = Bs1 + lo * BS1_ST;
            #pragma unroll
            for (int j = 0; j < 4; j++) *(uint4*)(dB + (lq4 * 4 + j) * 4) = f2tf4(pb[j]);
        }
        __syncthreads();

        if (kc + 1 < K_) {   // prefetch next chunk — overlaps the mma block below
            const float4* sA = (const float4*)(x + offs[lr * K_ + kc + 1]) + lh * 8;
            #pragma unroll
            for (int j = 0; j < 8; j++) pa[j] = sA[j];
            const float4* sB = (const float4*)(W1 + lo * KIN1_ + (kc + 1) * PC_);
            #pragma unroll
            for (int j = 0; j < 4; j++) pb[j] = sB[lq4 * 4 + j];
        }

        #pragma unroll
        for (int kk = 0; kk < PC_; kk += 8) {
            unsigned a[2][4];
            #pragma unroll
            for (int ms = 0; ms < 2; ms++) {
                const unsigned* p = As1 + (wm * 32 + ms * 16 + lg) * AS1_ST + kk + lq;
                a[ms][0] = p[0];
                a[ms][1] = p[8 * AS1_ST];
                a[ms][2] = p[4];
                a[ms][3] = p[8 * AS1_ST + 4];
            }
            #pragma unroll
            for (int ns = 0; ns < 4; ns++) {
                const unsigned* p = Bs1 + (wn * 32 + ns * 8 + lg) * BS1_ST + kk + lq;
                unsigned u0 = p[0], u1 = p[4];
                mma8(acc1[0][ns], a[0], u0, u1);
                mma8(acc1[1][ns], a[1], u0, u1);
            }
        }
        __syncthreads();
    }

    // ---- P epilogue: + b1, tf32, into Af cols [0,64) ----
    #pragma unroll
    for (int ms = 0; ms < 2; ms++) {
        #pragma unroll
        for (int ns = 0; ns < 4; ns++) {
            int row = wm * 32 + ms * 16 + lg;
            int col = wn * 32 + ns * 8 + lq * 2;
            float bv0 = b1[col], bv1 = b1[col + 1];
            *(uint2*)(Af + row * AF_ST + col) =
                make_uint2(f2tf(acc1[ms][ns][0] + bv0), f2tf(acc1[ms][ns][1] + bv1));
            *(uint2*)(Af + (row + 8) * AF_ST + col) =
                make_uint2(f2tf(acc1[ms][ns][2] + bv0), f2tf(acc1[ms][ns][3] + bv1));
        }
    }
    __syncthreads();

    bias2[tid] = b2[tid];

    // ================= Phase 2: out = Af(128x256) @ W2^T + b2 =================
    const int loB = tid >> 1, lhB = tid & 1;  // B loader: out-row, half(16 floats)
    float4 pw[4];

    #pragma unroll
    for (int nc = 0; nc < 2; nc++) {
        float acc2[2][8][4];
        #pragma unroll
        for (int i = 0; i < 2; i++)
            #pragma unroll
            for (int j = 0; j < 8; j++)
                #pragma unroll
                for (int l = 0; l < 4; l++) acc2[i][j][l] = 0.f;

        {   // prologue prefetch: W2[nc*128 + loB][0..32)
            const float4* sB = (const float4*)(W2 + (size_t)(nc * 128 + loB) * C_);
            #pragma unroll
            for (int j = 0; j < 4; j++) pw[j] = sB[lhB * 4 + j];
        }

        for (int kc = 0; kc < 8; kc++) {
            __syncthreads();   // prior Bs2 readers done (also covers bias2/P writes)
            {   // STS prefetched W2 slab
                unsigned* dB = Bs2 + loB * BS2_ST + lhB * 16;
                #pragma unroll
                for (int j = 0; j < 4; j++) *(uint4*)(dB + j * 4) = f2tf4(pw[j]);
            }
            __syncthreads();

            if (kc + 1 < 8) {   // prefetch next slab — overlaps mma below
                const float4* sB =
                    (const float4*)(W2 + (size_t)(nc * 128 + loB) * C_ + (kc + 1) * 32);
                #pragma unroll
                for (int j = 0; j < 4; j++) pw[j] = sB[lhB * 4 + j];
            }

            #pragma unroll
            for (int kk = 0; kk < 32; kk += 8) {
                unsigned a[2][4];
                #pragma unroll
                for (int ms = 0; ms < 2; ms++) {
                    const unsigned* p =
                        Af + (wm * 32 + ms * 16 + lg) * AF_ST + kc * 32 + kk + lq;
                    a[ms][0] = p[0];
                    a[ms][1] = p[8 * AF_ST];
                    a[ms][2] = p[4];
                    a[ms][3] = p[8 * AF_ST + 4];
                }
                #pragma unroll
                for (int ns = 0; ns < 8; ns++) {
                    const unsigned* p = Bs2 + (wn * 64 + ns * 8 + lg) * BS2_ST + kk + lq;
                    unsigned u0 = p[0], u1 = p[4];
                    mma8(acc2[0][ns], a[0], u0, u1);
                    mma8(acc2[1][ns], a[1], u0, u1);
                }
            }
        }

        // epilogue: + b2, store out cols [nc*128, nc*128+128)
        #pragma unroll
        for (int ms = 0; ms < 2; ms++) {
            #pragma unroll
            for (int ns = 0; ns < 8; ns++) {
                int row = m0 + wm * 32 + ms * 16 + lg;
                int col = nc * 128 + wn * 64 + ns * 8 + lq * 2;
                float bv0 = bias2[col], bv1 = bias2[col + 1];
                *(float2*)(out + (size_t)row * C_ + col) =
                    make_float2(acc2[ms][ns][0] + bv0, acc2[ms][ns][1] + bv1);
                *(float2*)(out + (size_t)(row + 8) * C_ + col) =
                    make_float2(acc2[ms][ns][2] + bv0, acc2[ms][ns][3] + bv1);
            }
        }
    }
}

extern "C" void kernel_launch(void* const* d_in, const int* in_sizes, int n_in,
                              void* d_out, int out_size) {
    const float* x   = (const float*)d_in[0];
    const int*   idx = (const int*)d_in[1];
    const float* W1  = (const float*)d_in[2];
    const float* b1  = (const float*)d_in[3];
    const float* W2  = (const float*)d_in[4];
    const float* b2  = (const float*)d_in[5];
    float*       out = (float*)d_out;

    const int smem = SMEM_WORDS * 4;   // 189952 bytes
    cudaFuncSetAttribute(fused_spiral, cudaFuncAttributeMaxDynamicSharedMemorySize, smem);
    fused_spiral<<<M_TOTAL / TILE_M, 256, smem>>>(x, idx, W1, b1, W2, b2, out);
}